// round 7
// baseline (speedup 1.0000x reference)
#include <cuda_runtime.h>
#include <cuda_bf16.h>

#define N_SAMPLE 12
#define D_FEAT 64
#define NODES_PER_WARP 4
#define BLOCKS_PERSISTENT 740   // 148 SMs x 5 blocks/SM (regs=47) = one wave

__global__ void __launch_bounds__(256)
mean_agg_kernel(const float* __restrict__ feature,
                const int* __restrict__ neighbor_idx,
                float* __restrict__ out,
                int n_nodes) {
    int lane = threadIdx.x & 31;
    int g    = lane >> 3;   // group 0..3 -> node within warp
    int lg   = lane & 7;    // lane in group: owns 8 floats (32 B) of the row

    int warp_in_grid = (int)((blockIdx.x * (unsigned)blockDim.x + threadIdx.x) >> 5);
    int warps_total  = (int)((gridDim.x * (unsigned)blockDim.x) >> 5);

    int n_warp_tiles = (n_nodes + NODES_PER_WARP - 1) / NODES_PER_WARP;

    for (int tile = warp_in_grid; tile < n_warp_tiles; tile += warps_total) {
        int node   = tile * NODES_PER_WARP + g;
        bool active = node < n_nodes;
        int node_c = active ? node : 0;

        // 12 indices per group: lanes 0..7 hold samples 0..7, lanes 0..3
        // additionally hold samples 8..11.
        const int* ibase = neighbor_idx + (long long)node_c * N_SAMPLE;
        int idx_a = ibase[lg];
        int idx_b = (lg < 4) ? ibase[8 + lg] : 0;

        float a0=0.f,a1=0.f,a2=0.f,a3=0.f,a4=0.f,a5=0.f,a6=0.f,a7=0.f;

#pragma unroll
        for (int s = 0; s < N_SAMPLE; s++) {
            int src = g * 8 + (s < 8 ? s : s - 8);
            int id  = __shfl_sync(0xffffffffu, (s < 8) ? idx_a : idx_b, src);
            const float* fp = feature + (long long)id * D_FEAT + lg * 8;
            unsigned r0,r1,r2,r3,r4,r5,r6,r7;
            // 256-bit gather, pinned in L2 (feature reused ~6x per launch).
            asm volatile("ld.global.nc.L2::evict_last.v8.b32 "
                         "{%0,%1,%2,%3,%4,%5,%6,%7}, [%8];"
                         : "=r"(r0),"=r"(r1),"=r"(r2),"=r"(r3),
                           "=r"(r4),"=r"(r5),"=r"(r6),"=r"(r7)
                         : "l"(fp));
            a0 += __uint_as_float(r0); a1 += __uint_as_float(r1);
            a2 += __uint_as_float(r2); a3 += __uint_as_float(r3);
            a4 += __uint_as_float(r4); a5 += __uint_as_float(r5);
            a6 += __uint_as_float(r6); a7 += __uint_as_float(r7);
        }

        const float inv = 1.0f / (float)N_SAMPLE;
        if (active) {
            float* op = out + (long long)node * D_FEAT + lg * 8;
            unsigned w0 = __float_as_uint(a0 * inv), w1 = __float_as_uint(a1 * inv);
            unsigned w2 = __float_as_uint(a2 * inv), w3 = __float_as_uint(a3 * inv);
            unsigned w4 = __float_as_uint(a4 * inv), w5 = __float_as_uint(a5 * inv);
            unsigned w6 = __float_as_uint(a6 * inv), w7 = __float_as_uint(a7 * inv);
            // Streaming write-once output: don't evict feature lines.
            asm volatile("st.global.L2::evict_first.v8.b32 [%0], "
                         "{%1,%2,%3,%4,%5,%6,%7,%8};"
                         :: "l"(op),
                            "r"(w0),"r"(w1),"r"(w2),"r"(w3),
                            "r"(w4),"r"(w5),"r"(w6),"r"(w7)
                         : "memory");
        }
    }
}

extern "C" void kernel_launch(void* const* d_in, const int* in_sizes, int n_in,
                              void* d_out, int out_size) {
    const float* feature      = (const float*)d_in[0];
    const int*   neighbor_idx = (const int*)d_in[1];
    float*       out          = (float*)d_out;

    int n_nodes = in_sizes[1] / N_SAMPLE;

    mean_agg_kernel<<<BLOCKS_PERSISTENT, 256>>>(feature, neighbor_idx, out, n_nodes);
}

// round 8
// speedup vs baseline: 1.2187x; 1.2187x over previous
#include <cuda_runtime.h>
#include <cuda_bf16.h>

#define N_SAMPLE 12
#define D_FEAT 64
#define NODES_PER_WARP 4

template <bool GUARDED>
__global__ void __launch_bounds__(256)
mean_agg_kernel(const float* __restrict__ feature,
                const int* __restrict__ neighbor_idx,
                float* __restrict__ out,
                int n_nodes) {
    int gwarp = (int)((blockIdx.x * (unsigned)blockDim.x + threadIdx.x) >> 5);
    int lane  = threadIdx.x & 31;
    int g     = lane >> 3;   // group 0..3 -> node within warp
    int lg    = lane & 7;    // lane in group: owns 8 floats (32 B) of the row

    int node = gwarp * NODES_PER_WARP + g;
    bool active = true;
    if (GUARDED) {
        active = node < n_nodes;
        if (!active) node = 0;   // clamp so inactive lanes load safely
    }

    // 12 indices per group: lanes 0..7 hold samples 0..7 (idx_a),
    // lanes 0..3 additionally hold samples 8..11 (idx_b).
    const int* ibase = neighbor_idx + (long long)node * N_SAMPLE;
    int idx_a = ibase[lg];
    int idx_b = (lg < 4) ? ibase[8 + lg] : 0;

    float a0=0.f,a1=0.f,a2=0.f,a3=0.f,a4=0.f,a5=0.f,a6=0.f,a7=0.f;

#pragma unroll
    for (int s = 0; s < N_SAMPLE; s++) {
        int src = g * 8 + (s < 8 ? s : s - 8);
        int id  = __shfl_sync(0xffffffffu, (s < 8) ? idx_a : idx_b, src);
        const float* fp = feature + (long long)id * D_FEAT + lg * 8;
        unsigned r0,r1,r2,r3,r4,r5,r6,r7;
        // 256-bit gather, pinned in L2 (feature reused ~6x per launch).
        asm volatile("ld.global.nc.L2::evict_last.v8.b32 "
                     "{%0,%1,%2,%3,%4,%5,%6,%7}, [%8];"
                     : "=r"(r0),"=r"(r1),"=r"(r2),"=r"(r3),
                       "=r"(r4),"=r"(r5),"=r"(r6),"=r"(r7)
                     : "l"(fp));
        a0 += __uint_as_float(r0); a1 += __uint_as_float(r1);
        a2 += __uint_as_float(r2); a3 += __uint_as_float(r3);
        a4 += __uint_as_float(r4); a5 += __uint_as_float(r5);
        a6 += __uint_as_float(r6); a7 += __uint_as_float(r7);
    }

    const float inv = 1.0f / (float)N_SAMPLE;
    if (!GUARDED || active) {
        float* op = out + (long long)node * D_FEAT + lg * 8;
        unsigned w0 = __float_as_uint(a0 * inv), w1 = __float_as_uint(a1 * inv);
        unsigned w2 = __float_as_uint(a2 * inv), w3 = __float_as_uint(a3 * inv);
        unsigned w4 = __float_as_uint(a4 * inv), w5 = __float_as_uint(a5 * inv);
        unsigned w6 = __float_as_uint(a6 * inv), w7 = __float_as_uint(a7 * inv);
        // Streaming write-once output: don't evict feature lines.
        asm volatile("st.global.L2::evict_first.v8.b32 [%0], "
                     "{%1,%2,%3,%4,%5,%6,%7,%8};"
                     :: "l"(op),
                        "r"(w0),"r"(w1),"r"(w2),"r"(w3),
                        "r"(w4),"r"(w5),"r"(w6),"r"(w7)
                     : "memory");
    }
}

extern "C" void kernel_launch(void* const* d_in, const int* in_sizes, int n_in,
                              void* d_out, int out_size) {
    const float* feature      = (const float*)d_in[0];
    const int*   neighbor_idx = (const int*)d_in[1];
    float*       out          = (float*)d_out;

    int n_nodes = in_sizes[1] / N_SAMPLE;

    const int nodes_per_block = (256 / 32) * NODES_PER_WARP;  // 32
    int blocks = (n_nodes + nodes_per_block - 1) / nodes_per_block;

    if (n_nodes % nodes_per_block == 0) {
        // Exact cover (the benchmark shape: 100000 = 3125 * 32) — no guards.
        mean_agg_kernel<false><<<blocks, 256>>>(feature, neighbor_idx, out, n_nodes);
    } else {
        mean_agg_kernel<true><<<blocks, 256>>>(feature, neighbor_idx, out, n_nodes);
    }
}

// round 9
// speedup vs baseline: 1.2775x; 1.0483x over previous
#include <cuda_runtime.h>
#include <cuda_bf16.h>

#define N_SAMPLE 12
#define D_FEAT 64
#define NODES_PER_WARP 4
#define HALF 6

__device__ __forceinline__ void gather_v8(const float* __restrict__ fp,
                                          unsigned* r) {
    asm volatile("ld.global.nc.L2::evict_last.v8.b32 "
                 "{%0,%1,%2,%3,%4,%5,%6,%7}, [%8];"
                 : "=r"(r[0]),"=r"(r[1]),"=r"(r[2]),"=r"(r[3]),
                   "=r"(r[4]),"=r"(r[5]),"=r"(r[6]),"=r"(r[7])
                 : "l"(fp));
}

template <bool GUARDED>
__global__ void __launch_bounds__(256, 4)
mean_agg_kernel(const float* __restrict__ feature,
                const int* __restrict__ neighbor_idx,
                float* __restrict__ out,
                int n_nodes) {
    int gwarp = (int)((blockIdx.x * (unsigned)blockDim.x + threadIdx.x) >> 5);
    int lane  = threadIdx.x & 31;
    int g     = lane >> 3;   // group 0..3 -> node within warp
    int lg    = lane & 7;    // lane in group: owns 8 floats (32 B) of the row

    int node = gwarp * NODES_PER_WARP + g;
    bool active = true;
    if (GUARDED) {
        active = node < n_nodes;
        if (!active) node = 0;   // clamp so inactive lanes load safely
    }

    // 12 indices per group: lanes 0..7 hold samples 0..7 (idx_a),
    // lanes 0..3 additionally hold samples 8..11 (idx_b).
    const int* ibase = neighbor_idx + (long long)node * N_SAMPLE;
    int idx_a = ibase[lg];
    int idx_b = (lg < 4) ? ibase[8 + lg] : 0;

    const float* fbase = feature + (long long)lg * 8;

    float acc[8];
#pragma unroll
    for (int k = 0; k < 8; k++) acc[k] = 0.f;

    // Software pipeline: keep ~6 v8 gathers (192 B/lane) in flight.
    unsigned buf[HALF][8];

    // Prologue: issue samples 0..5.
#pragma unroll
    for (int s = 0; s < HALF; s++) {
        int id = __shfl_sync(0xffffffffu, idx_a, g * 8 + s);
        gather_v8(fbase + (long long)id * D_FEAT, buf[s]);
    }

    // Steady state: for each consumed sample s, issue sample s+6 first.
#pragma unroll
    for (int s = 0; s < HALF; s++) {
        int s2 = s + HALF;  // 6..11
        int src = g * 8 + (s2 < 8 ? s2 : s2 - 8);
        int id  = __shfl_sync(0xffffffffu, (s2 < 8) ? idx_a : idx_b, src);
        unsigned nxt[8];
        gather_v8(fbase + (long long)id * D_FEAT, nxt);
#pragma unroll
        for (int k = 0; k < 8; k++) acc[k] += __uint_as_float(buf[s][k]);
#pragma unroll
        for (int k = 0; k < 8; k++) buf[s][k] = nxt[k];
    }

    // Epilogue: consume samples 6..11.
#pragma unroll
    for (int s = 0; s < HALF; s++) {
#pragma unroll
        for (int k = 0; k < 8; k++) acc[k] += __uint_as_float(buf[s][k]);
    }

    const float inv = 1.0f / (float)N_SAMPLE;
    if (!GUARDED || active) {
        float* op = out + (long long)node * D_FEAT + lg * 8;
        unsigned w[8];
#pragma unroll
        for (int k = 0; k < 8; k++) w[k] = __float_as_uint(acc[k] * inv);
        // Streaming write-once output: don't evict feature lines.
        asm volatile("st.global.L2::evict_first.v8.b32 [%0], "
                     "{%1,%2,%3,%4,%5,%6,%7,%8};"
                     :: "l"(op),
                        "r"(w[0]),"r"(w[1]),"r"(w[2]),"r"(w[3]),
                        "r"(w[4]),"r"(w[5]),"r"(w[6]),"r"(w[7])
                     : "memory");
    }
}

extern "C" void kernel_launch(void* const* d_in, const int* in_sizes, int n_in,
                              void* d_out, int out_size) {
    const float* feature      = (const float*)d_in[0];
    const int*   neighbor_idx = (const int*)d_in[1];
    float*       out          = (float*)d_out;

    int n_nodes = in_sizes[1] / N_SAMPLE;

    const int nodes_per_block = (256 / 32) * NODES_PER_WARP;  // 32
    int blocks = (n_nodes + nodes_per_block - 1) / nodes_per_block;

    if (n_nodes % nodes_per_block == 0) {
        // Exact cover (the benchmark shape: 100000 = 3125 * 32) — no guards.
        mean_agg_kernel<false><<<blocks, 256>>>(feature, neighbor_idx, out, n_nodes);
    } else {
        mean_agg_kernel<true><<<blocks, 256>>>(feature, neighbor_idx, out, n_nodes);
    }
}